// round 6
// baseline (speedup 1.0000x reference)
#include <cuda_runtime.h>
#include <math.h>

// ---------------- problem constants (fixed shapes for this problem) ----------
#define NB   4
#define NN   65536
#define NTOK (NB*NN)        // 262144 tokens
#define CD   256
#define LD   64
#define SD   64
#define AD   16

#define TT     16           // tokens per tile
#define TPB    256          // threads per block
#define TILES  16           // tiles per block
#define TOKBLK (TT*TILES)   // 256 tokens per block
#define GRID_BN (NTOK/TOKBLK) // 1024 blocks
#define BLK_PER_BATCH (NN/TOKBLK) // 256

// ---------------- scratch (no cudaMalloc allowed) ----------------------------
__device__ float g_w[(size_t)NTOK*SD];               // 64 MB softmax assignments
__device__ float g_partA[(size_t)GRID_BN*SD*CD];     // 64 MB per-block slice partials
__device__ float g_partW[GRID_BN*SD];                // wsum partials
__device__ float g_slice[NB*SD*CD];                  // reduced slice tokens (already /wsum)
__device__ float g_st[NB*SD*CD];                     // latent-transition output

// ---------------- helpers ----------------------------------------------------
__device__ __forceinline__ float wsum32(float v) {
#pragma unroll
    for (int o = 16; o; o >>= 1) v += __shfl_xor_sync(0xffffffffu, v, o);
    return v;
}
__device__ __forceinline__ float wmax32(float v) {
#pragma unroll
    for (int o = 16; o; o >>= 1) v = fmaxf(v, __shfl_xor_sync(0xffffffffu, v, o));
    return v;
}
__device__ __forceinline__ float gelu_exact(float x) {
    return 0.5f * x * (1.f + erff(x * 0.70710678118654752440f));
}

// =============================================================================
// Pass A: LN1 -> shared -> feat -> logits -> softmax(w) -> partial scatter
// =============================================================================
__global__ __launch_bounds__(TPB, 2)
void kA(const float* __restrict__ x, const float* __restrict__ geom,
        const float* __restrict__ ln1g, const float* __restrict__ ln1b,
        const float* __restrict__ Wsh, const float* __restrict__ bsh,
        const float* __restrict__ Wf,  const float* __restrict__ bf,
        const float* __restrict__ Wa,  const float* __restrict__ ba)
{
    extern __shared__ float smem[];
    float* h_s    = smem;                 // TT*CD = 4096 (x tile, then h)
    float* sh_s   = h_s   + TT*CD;        // TT*LD = 1024
    float* feat_s = sh_s  + TT*LD;        // TT*CD = 4096
    float* ge_s   = feat_s + TT*CD;       // TT*LD = 1024
    float* w_s    = ge_s  + TT*LD;        // TT*LD = 1024 (logits, then w)

    const int tid  = threadIdx.x;
    const int bid  = blockIdx.x;
    const size_t tokbase = (size_t)bid * TOKBLK;

    float acc_s[SD];
#pragma unroll
    for (int s = 0; s < SD; ++s) acc_s[s] = 0.f;
    float wacc = 0.f;

    const int wid = tid >> 5, lane = tid & 31;
    const int lcol = tid & 63, tq = tid >> 6;   // for 4-output mappings

#pragma unroll 1
    for (int tile = 0; tile < TILES; ++tile) {
        const size_t t0 = tokbase + (size_t)tile * TT;

        // ---- load x tile (float4) and geometry tile ----
        {
            const float4* xg = (const float4*)(x + t0 * CD);
            float4* hv = (float4*)h_s;
#pragma unroll
            for (int q = tid; q < TT*CD/4; q += TPB) hv[q] = xg[q];
            const float4* gg = (const float4*)(geom + t0 * LD);
            float4* gv = (float4*)ge_s;
#pragma unroll
            for (int q = tid; q < TT*LD/4; q += TPB) gv[q] = gg[q];
        }
        __syncthreads();

        // ---- LN1: warp handles 2 tokens ----
        {
#pragma unroll
            for (int t = wid*2; t < wid*2 + 2; ++t) {
                float v[8]; float sum = 0.f;
#pragma unroll
                for (int i = 0; i < 8; ++i) { v[i] = h_s[t*CD + i*32 + lane]; sum += v[i]; }
                sum = wsum32(sum);
                const float mean = sum * (1.f/256.f);
                float sq = 0.f;
#pragma unroll
                for (int i = 0; i < 8; ++i) { float d = v[i]-mean; sq += d*d; }
                sq = wsum32(sq);
                const float rs = rsqrtf(sq * (1.f/256.f) + 1e-5f);
#pragma unroll
                for (int i = 0; i < 8; ++i) {
                    const int c = i*32 + lane;
                    h_s[t*CD + c] = (v[i]-mean)*rs*__ldg(ln1g+c) + __ldg(ln1b+c);
                }
            }
        }
        __syncthreads();

        // ---- shared = h @ Wsh + bsh : thread -> (l=lcol, toks tq,tq+4,tq+8,tq+12)
        // float4 LDS on h rows (broadcast within 64-thread groups)
        {
            float a0 = __ldg(bsh + lcol); float a1 = a0, a2 = a0, a3 = a0;
            const float4* h0 = (const float4*)(h_s + (tq   )*CD);
            const float4* h1 = (const float4*)(h_s + (tq+ 4)*CD);
            const float4* h2 = (const float4*)(h_s + (tq+ 8)*CD);
            const float4* h3 = (const float4*)(h_s + (tq+12)*CD);
#pragma unroll 4
            for (int c4 = 0; c4 < CD/4; ++c4) {
                const int c = c4*4;
                const float w0 = __ldg(Wsh + (c  )*LD + lcol);
                const float w1 = __ldg(Wsh + (c+1)*LD + lcol);
                const float w2 = __ldg(Wsh + (c+2)*LD + lcol);
                const float w3 = __ldg(Wsh + (c+3)*LD + lcol);
                float4 v;
                v = h0[c4]; a0 += v.x*w0 + v.y*w1 + v.z*w2 + v.w*w3;
                v = h1[c4]; a1 += v.x*w0 + v.y*w1 + v.z*w2 + v.w*w3;
                v = h2[c4]; a2 += v.x*w0 + v.y*w1 + v.z*w2 + v.w*w3;
                v = h3[c4]; a3 += v.x*w0 + v.y*w1 + v.z*w2 + v.w*w3;
            }
            sh_s[(tq   )*LD + lcol] = a0;
            sh_s[(tq+ 4)*LD + lcol] = a1;
            sh_s[(tq+ 8)*LD + lcol] = a2;
            sh_s[(tq+12)*LD + lcol] = a3;
        }
        __syncthreads();

        // ---- feat = shared @ Wf + bf : thread -> (c=tid, toks 0..15)
        {
            float fa[TT];
            const float fb = __ldg(bf + tid);
#pragma unroll
            for (int t = 0; t < TT; ++t) fa[t] = fb;
#pragma unroll 2
            for (int l4 = 0; l4 < LD/4; ++l4) {
                const int l = l4*4;
                const float w0 = __ldg(Wf + (l  )*CD + tid);
                const float w1 = __ldg(Wf + (l+1)*CD + tid);
                const float w2 = __ldg(Wf + (l+2)*CD + tid);
                const float w3 = __ldg(Wf + (l+3)*CD + tid);
#pragma unroll
                for (int t = 0; t < TT; ++t) {
                    const float4 sv = ((const float4*)(sh_s + t*LD))[l4];
                    fa[t] += sv.x*w0 + sv.y*w1 + sv.z*w2 + sv.w*w3;
                }
            }
#pragma unroll
            for (int t = 0; t < TT; ++t) feat_s[t*CD + tid] = fa[t];
        }

        // ---- logits = [shared, geom] @ Wa + ba  (reads sh_s/ge_s only; no sync needed)
        {
            float a0 = __ldg(ba + lcol); float a1 = a0, a2 = a0, a3 = a0;
#pragma unroll 4
            for (int k4 = 0; k4 < LD/4; ++k4) {
                const int k = k4*4;
                const float w0 = __ldg(Wa + (k  )*SD + lcol);
                const float w1 = __ldg(Wa + (k+1)*SD + lcol);
                const float w2 = __ldg(Wa + (k+2)*SD + lcol);
                const float w3 = __ldg(Wa + (k+3)*SD + lcol);
                float4 v;
                v = ((const float4*)(sh_s + (tq   )*LD))[k4]; a0 += v.x*w0 + v.y*w1 + v.z*w2 + v.w*w3;
                v = ((const float4*)(sh_s + (tq+ 4)*LD))[k4]; a1 += v.x*w0 + v.y*w1 + v.z*w2 + v.w*w3;
                v = ((const float4*)(sh_s + (tq+ 8)*LD))[k4]; a2 += v.x*w0 + v.y*w1 + v.z*w2 + v.w*w3;
                v = ((const float4*)(sh_s + (tq+12)*LD))[k4]; a3 += v.x*w0 + v.y*w1 + v.z*w2 + v.w*w3;
            }
#pragma unroll 4
            for (int k4 = 0; k4 < LD/4; ++k4) {
                const int k = k4*4;
                const float w0 = __ldg(Wa + (LD+k  )*SD + lcol);
                const float w1 = __ldg(Wa + (LD+k+1)*SD + lcol);
                const float w2 = __ldg(Wa + (LD+k+2)*SD + lcol);
                const float w3 = __ldg(Wa + (LD+k+3)*SD + lcol);
                float4 v;
                v = ((const float4*)(ge_s + (tq   )*LD))[k4]; a0 += v.x*w0 + v.y*w1 + v.z*w2 + v.w*w3;
                v = ((const float4*)(ge_s + (tq+ 4)*LD))[k4]; a1 += v.x*w0 + v.y*w1 + v.z*w2 + v.w*w3;
                v = ((const float4*)(ge_s + (tq+ 8)*LD))[k4]; a2 += v.x*w0 + v.y*w1 + v.z*w2 + v.w*w3;
                v = ((const float4*)(ge_s + (tq+12)*LD))[k4]; a3 += v.x*w0 + v.y*w1 + v.z*w2 + v.w*w3;
            }
            w_s[(tq   )*LD + lcol] = a0;
            w_s[(tq+ 4)*LD + lcol] = a1;
            w_s[(tq+ 8)*LD + lcol] = a2;
            w_s[(tq+12)*LD + lcol] = a3;
        }
        __syncthreads();

        // ---- softmax over S=64, warp per 2 tokens; also write w to global ----
        {
#pragma unroll
            for (int t = wid*2; t < wid*2 + 2; ++t) {
                float v0 = w_s[t*LD + lane], v1 = w_s[t*LD + lane + 32];
                float m = wmax32(fmaxf(v0, v1));
                float e0 = __expf(v0 - m), e1 = __expf(v1 - m);
                float s = wsum32(e0 + e1);
                const float inv = 1.f / s;
                e0 *= inv; e1 *= inv;
                w_s[t*LD + lane]      = e0;
                w_s[t*LD + lane + 32] = e1;
                const size_t tok = t0 + t;
                g_w[tok*SD + lane]      = e0;
                g_w[tok*SD + lane + 32] = e1;
            }
        }
        __syncthreads();

        // ---- scatter: acc[s] += w[t][s] * feat[t][tid], float4 on w row ----
        {
#pragma unroll 1
            for (int t = 0; t < TT; ++t) {
                const float fr = feat_s[t*CD + tid];
                const float4* wv4 = (const float4*)(w_s + t*LD);
#pragma unroll
                for (int s4 = 0; s4 < SD/4; ++s4) {
                    const float4 w = wv4[s4];
                    acc_s[4*s4+0] += w.x * fr;
                    acc_s[4*s4+1] += w.y * fr;
                    acc_s[4*s4+2] += w.z * fr;
                    acc_s[4*s4+3] += w.w * fr;
                }
            }
            if (tid < SD) {
#pragma unroll
                for (int t = 0; t < TT; ++t) wacc += w_s[t*LD + tid];
            }
        }
        __syncthreads();
    }

    // ---- flush per-block partials ----
#pragma unroll
    for (int s = 0; s < SD; ++s)
        g_partA[((size_t)bid*SD + s)*CD + tid] = acc_s[s];
    if (tid < SD) g_partW[bid*SD + tid] = wacc;
}

// =============================================================================
// Reduce partials -> g_slice (already divided by clamp(wsum))
// =============================================================================
__global__ void kR()
{
    const int b = blockIdx.x >> 6;       // batch
    const int s = blockIdx.x & 63;       // slice
    const int tid = threadIdx.x;
    __shared__ float red[TPB];
    red[tid] = g_partW[(b*BLK_PER_BATCH + tid)*SD + s];
    __syncthreads();
#pragma unroll
    for (int o = 128; o; o >>= 1) {
        if (tid < o) red[tid] += red[tid + o];
        __syncthreads();
    }
    const float inv = 1.f / fmaxf(red[0], 1e-6f);
    float acc = 0.f;
#pragma unroll 4
    for (int k = 0; k < BLK_PER_BATCH; ++k)
        acc += g_partA[(((size_t)(b*BLK_PER_BATCH + k))*SD + s)*CD + tid];
    g_slice[((b<<6) + s)*CD + tid] = acc * inv;
}

// =============================================================================
// Pass B: LatentTransition (tiny: 64 rows per batch). One block per batch.
// =============================================================================
__global__ void kB(const float* __restrict__ ltdW, const float* __restrict__ ltdb,
                   const float* __restrict__ dng,  const float* __restrict__ dnb,
                   const float* __restrict__ ancW, const float* __restrict__ ancb,
                   const float* __restrict__ selfW,const float* __restrict__ ctxW,
                   const float* __restrict__ ong,  const float* __restrict__ onb,
                   const float* __restrict__ upW,  const float* __restrict__ upb)
{
    extern __shared__ float sm[];
    float* raw  = sm;            // 4096  (ds raw, later ul)
    float* ls   = raw  + 4096;   // 4096  (ls, later uln)
    float* aw   = ls   + 4096;   // 1024
    float* anc  = aw   + 1024;   // 1024
    float* ctx  = anc  + 1024;   // 4096
    float* asum = ctx  + 4096;   // 16

    const int b = blockIdx.x;
    const int tid = threadIdx.x;
    const float* sl = g_slice + (size_t)b*SD*CD;

    // s1: raw = slice @ lt_down_W + b
    for (int idx = tid; idx < SD*LD; idx += TPB) {
        const int r = idx >> 6, l = idx & 63;
        float acc = __ldg(ltdb + l);
#pragma unroll 4
        for (int c = 0; c < CD; ++c) acc += __ldg(sl + r*CD + c) * __ldg(ltdW + c*LD + l);
        raw[idx] = acc;
    }
    __syncthreads();
    // s2: LN rows -> ls
    if (tid < SD) {
        const int r = tid;
        float m = 0.f;
#pragma unroll
        for (int l = 0; l < LD; ++l) m += raw[r*LD + l];
        m *= (1.f/64.f);
        float v = 0.f;
#pragma unroll
        for (int l = 0; l < LD; ++l) { float d = raw[r*LD + l] - m; v += d*d; }
        const float rs = rsqrtf(v*(1.f/64.f) + 1e-5f);
#pragma unroll
        for (int l = 0; l < LD; ++l)
            ls[r*LD + l] = (raw[r*LD + l] - m)*rs*__ldg(dng+l) + __ldg(dnb+l);
    }
    __syncthreads();
    // s3: anchor logits -> aw
    for (int idx = tid; idx < SD*AD; idx += TPB) {
        const int r = idx >> 4, a = idx & 15;
        float acc = __ldg(ancb + a);
#pragma unroll
        for (int l = 0; l < LD; ++l) acc += ls[r*LD + l] * __ldg(ancW + l*AD + a);
        aw[idx] = acc;
    }
    __syncthreads();
    // s4: softmax rows over A=16
    if (tid < SD) {
        const int r = tid;
        float m = -1e30f;
#pragma unroll
        for (int a = 0; a < AD; ++a) m = fmaxf(m, aw[r*AD + a]);
        float s = 0.f;
#pragma unroll
        for (int a = 0; a < AD; ++a) { float e = __expf(aw[r*AD + a] - m); aw[r*AD + a] = e; s += e; }
        const float inv = 1.f / s;
#pragma unroll
        for (int a = 0; a < AD; ++a) aw[r*AD + a] *= inv;
    }
    __syncthreads();
    // s5: asum
    if (tid < AD) {
        float s = 0.f;
#pragma unroll
        for (int r = 0; r < SD; ++r) s += aw[r*AD + tid];
        asum[tid] = s;
    }
    __syncthreads();
    // s6: anchor
    for (int idx = tid; idx < AD*LD; idx += TPB) {
        const int a = idx >> 6, d = idx & 63;
        float acc = 0.f;
#pragma unroll
        for (int r = 0; r < SD; ++r) acc += aw[r*AD + a] * ls[r*LD + d];
        anc[idx] = acc / fmaxf(asum[a], 1e-6f);
    }
    __syncthreads();
    // s7: ctx
    for (int idx = tid; idx < SD*LD; idx += TPB) {
        const int r = idx >> 6, d = idx & 63;
        float acc = 0.f;
#pragma unroll
        for (int a = 0; a < AD; ++a) acc += aw[r*AD + a] * anc[a*LD + d];
        ctx[idx] = acc;
    }
    __syncthreads();
    // s8: ul = ls + gelu(ls@selfW + ctx@ctxW)  -> raw
    for (int idx = tid; idx < SD*LD; idx += TPB) {
        const int r = idx >> 6, d = idx & 63;
        float acc = 0.f;
#pragma unroll
        for (int l = 0; l < LD; ++l) acc += ls[r*LD + l] * __ldg(selfW + l*LD + d);
#pragma unroll
        for (int l = 0; l < LD; ++l) acc += ctx[r*LD + l] * __ldg(ctxW + l*LD + d);
        raw[idx] = ls[idx] + gelu_exact(acc);
    }
    __syncthreads();
    // s9: LN(ul) -> ls (uln)
    if (tid < SD) {
        const int r = tid;
        float m = 0.f;
#pragma unroll
        for (int l = 0; l < LD; ++l) m += raw[r*LD + l];
        m *= (1.f/64.f);
        float v = 0.f;
#pragma unroll
        for (int l = 0; l < LD; ++l) { float d = raw[r*LD + l] - m; v += d*d; }
        const float rs = rsqrtf(v*(1.f/64.f) + 1e-5f);
#pragma unroll
        for (int l = 0; l < LD; ++l)
            ls[r*LD + l] = (raw[r*LD + l] - m)*rs*__ldg(ong+l) + __ldg(onb+l);
    }
    __syncthreads();
    // s10: st = uln @ upW + upb
    for (int idx = tid; idx < SD*CD; idx += TPB) {
        const int r = idx >> 8, c = idx & 255;
        float acc = __ldg(upb + c);
#pragma unroll
        for (int l = 0; l < LD; ++l) acc += ls[r*LD + l] * __ldg(upW + l*CD + c);
        g_st[(size_t)b*SD*CD + idx] = acc;
    }
}

// =============================================================================
// Pass C: reader + residual, LN2, ChannelMixer GLU + residual -> out
// =============================================================================
__global__ __launch_bounds__(TPB, 2)
void kC(const float* __restrict__ x, float* __restrict__ out,
        const float* __restrict__ ln2g, const float* __restrict__ ln2b,
        const float* __restrict__ cinW, const float* __restrict__ cinb,
        const float* __restrict__ coutW,const float* __restrict__ coutb)
{
    extern __shared__ float smem[];
    float* st_s  = smem;                  // SD*CD = 16384
    float* x1_s  = st_s + SD*CD;          // TT*CD = 4096
    float* y_s   = x1_s + TT*CD;          // TT*CD = 4096
    float* vg_s  = y_s  + TT*CD;          // TT*128 = 2048
    float* wa_s  = vg_s + TT*2*LD;        // TT*LD = 1024 (w, then act)

    const int tid = threadIdx.x;
    const int bid = blockIdx.x;
    const size_t tokbase = (size_t)bid * TOKBLK;
    const int b = (int)(tokbase / NN);
    const int wid = tid >> 5, lane = tid & 31;

    // cache st for this batch
    {
        const float4* sg = (const float4*)(g_st + (size_t)b*SD*CD);
        float4* sv = (float4*)st_s;
#pragma unroll
        for (int q = tid; q < SD*CD/4; q += TPB) sv[q] = sg[q];
    }
    __syncthreads();

#pragma unroll 1
    for (int tile = 0; tile < TILES; ++tile) {
        const size_t t0 = tokbase + (size_t)tile * TT;

        // load x tile and w tile
        {
            const float4* xg = (const float4*)(x + t0 * CD);
            float4* xv = (float4*)x1_s;
#pragma unroll
            for (int q = tid; q < TT*CD/4; q += TPB) xv[q] = xg[q];
            const float4* wg = (const float4*)(g_w + t0 * SD);
            float4* wv = (float4*)wa_s;
#pragma unroll
            for (int q = tid; q < TT*SD/4; q += TPB) wv[q] = wg[q];
        }
        __syncthreads();

        // x1 = x + w @ st : thread owns column c=tid, all 16 tokens; float4 on w rows
        {
            float a1[TT];
#pragma unroll
            for (int t = 0; t < TT; ++t) a1[t] = x1_s[t*CD + tid];
#pragma unroll 2
            for (int s4 = 0; s4 < SD/4; ++s4) {
                const int s = s4*4;
                const float st0 = st_s[(s  )*CD + tid];
                const float st1 = st_s[(s+1)*CD + tid];
                const float st2 = st_s[(s+2)*CD + tid];
                const float st3 = st_s[(s+3)*CD + tid];
#pragma unroll
                for (int t = 0; t < TT; ++t) {
                    const float4 w = ((const float4*)(wa_s + t*SD))[s4];
                    a1[t] += w.x*st0 + w.y*st1 + w.z*st2 + w.w*st3;
                }
            }
#pragma unroll
            for (int t = 0; t < TT; ++t) x1_s[t*CD + tid] = a1[t];
        }
        __syncthreads();

        // LN2: warp per 2 tokens, x1_s -> y_s
        {
#pragma unroll
            for (int t = wid*2; t < wid*2 + 2; ++t) {
                float v[8]; float sum = 0.f;
#pragma unroll
                for (int i = 0; i < 8; ++i) { v[i] = x1_s[t*CD + i*32 + lane]; sum += v[i]; }
                sum = wsum32(sum);
                const float mean = sum * (1.f/256.f);
                float sq = 0.f;
#pragma unroll
                for (int i = 0; i < 8; ++i) { float d = v[i]-mean; sq += d*d; }
                sq = wsum32(sq);
                const float rs = rsqrtf(sq * (1.f/256.f) + 1e-5f);
#pragma unroll
                for (int i = 0; i < 8; ++i) {
                    const int c = i*32 + lane;
                    y_s[t*CD + c] = (v[i]-mean)*rs*__ldg(ln2g+c) + __ldg(ln2b+c);
                }
            }
        }
        __syncthreads();

        // vg = y @ cm_in_W + b : thread -> (j = tid&127, toks tt2, tt2+2, ..., tt2+14)
        {
            const int j = tid & 127, tt2 = tid >> 7;  // tt2 in {0,1}
            float acc[8];
            const float cb = __ldg(cinb + j);
#pragma unroll
            for (int k = 0; k < 8; ++k) acc[k] = cb;
#pragma unroll 2
            for (int c4 = 0; c4 < CD/4; ++c4) {
                const int c = c4*4;
                const float w0 = __ldg(cinW + (c  )*128 + j);
                const float w1 = __ldg(cinW + (c+1)*128 + j);
                const float w2 = __ldg(cinW + (c+2)*128 + j);
                const float w3 = __ldg(cinW + (c+3)*128 + j);
#pragma unroll
                for (int k = 0; k < 8; ++k) {
                    const float4 yv = ((const float4*)(y_s + (tt2 + 2*k)*CD))[c4];
                    acc[k] += yv.x*w0 + yv.y*w1 + yv.z*w2 + yv.w*w3;
                }
            }
#pragma unroll
            for (int k = 0; k < 8; ++k) vg_s[(tt2 + 2*k)*128 + j] = acc[k];
        }
        __syncthreads();

        // act = gelu(v) * sigmoid(g) -> wa_s
        for (int idx = tid; idx < TT*LD; idx += TPB) {
            const int t = idx >> 6, l = idx & 63;
            const float v = vg_s[t*128 + l];
            const float g = vg_s[t*128 + 64 + l];
            wa_s[idx] = gelu_exact(v) * (1.f / (1.f + __expf(-g)));
        }
        __syncthreads();

        // out = x1 + act @ cm_out_W + cm_out_b : thread owns column c=tid; float4 on act rows
        {
            float a2[TT];
            const float bo = __ldg(coutb + tid);
#pragma unroll
            for (int t = 0; t < TT; ++t) a2[t] = x1_s[t*CD + tid] + bo;
#pragma unroll 2
            for (int l4 = 0; l4 < LD/4; ++l4) {
                const int l = l4*4;
                const float w0 = __ldg(coutW + (l  )*CD + tid);
                const float w1 = __ldg(coutW + (l+1)*CD + tid);
                const float w2 = __ldg(coutW + (l+2)*CD + tid);
                const float w3 = __ldg(coutW + (l+3)*CD + tid);
#pragma unroll
                for (int t = 0; t < TT; ++t) {
                    const float4 av = ((const float4*)(wa_s + t*LD))[l4];
                    a2[t] += av.x*w0 + av.y*w1 + av.z*w2 + av.w*w3;
                }
            }
#pragma unroll
            for (int t = 0; t < TT; ++t) out[(t0 + t)*CD + tid] = a2[t];
        }
        __syncthreads();
    }
}

// =============================================================================
extern "C" void kernel_launch(void* const* d_in, const int* in_sizes, int n_in,
                              void* d_out, int out_size)
{
    const float* x     = (const float*)d_in[0];
    const float* geom  = (const float*)d_in[1];
    const float* ln1g  = (const float*)d_in[2];
    const float* ln1b  = (const float*)d_in[3];
    const float* Wsh   = (const float*)d_in[4];
    const float* bsh   = (const float*)d_in[5];
    const float* Wf    = (const float*)d_in[6];
    const float* bf    = (const float*)d_in[7];
    const float* Wa    = (const float*)d_in[8];
    const float* ba    = (const float*)d_in[9];
    const float* ltdW  = (const float*)d_in[10];
    const float* ltdb  = (const float*)d_in[11];
    const float* dng   = (const float*)d_in[12];
    const float* dnb   = (const float*)d_in[13];
    const float* ancW  = (const float*)d_in[14];
    const float* ancb  = (const float*)d_in[15];
    const float* selfW = (const float*)d_in[16];
    const float* ctxW  = (const float*)d_in[17];
    const float* ong   = (const float*)d_in[18];
    const float* onb   = (const float*)d_in[19];
    const float* upW   = (const float*)d_in[20];
    const float* upb   = (const float*)d_in[21];
    const float* ln2g  = (const float*)d_in[22];
    const float* ln2b  = (const float*)d_in[23];
    const float* cinW  = (const float*)d_in[24];
    const float* cinb  = (const float*)d_in[25];
    const float* coutW = (const float*)d_in[26];
    const float* coutb = (const float*)d_in[27];
    float* out = (float*)d_out;

    const int smemA = (TT*CD + TT*LD + TT*CD + TT*LD + TT*LD) * 4;           // 45056
    const int smemB = (4096 + 4096 + 1024 + 1024 + 4096 + 16) * 4;           // 57408
    const int smemC = (SD*CD + TT*CD + TT*CD + TT*2*LD + TT*LD) * 4;         // 110592

    cudaFuncSetAttribute(kA, cudaFuncAttributeMaxDynamicSharedMemorySize, smemA);
    cudaFuncSetAttribute(kB, cudaFuncAttributeMaxDynamicSharedMemorySize, smemB);
    cudaFuncSetAttribute(kC, cudaFuncAttributeMaxDynamicSharedMemorySize, smemC);

    kA<<<GRID_BN, TPB, smemA>>>(x, geom, ln1g, ln1b, Wsh, bsh, Wf, bf, Wa, ba);
    kR<<<NB*SD, TPB>>>();
    kB<<<NB, TPB, smemB>>>(ltdW, ltdb, dng, dnb, ancW, ancb, selfW, ctxW, ong, onb, upW, upb);
    kC<<<GRID_BN, TPB, smemC>>>(x, out, ln2g, ln2b, cinW, cinb, coutW, coutb);

    (void)in_sizes; (void)n_in; (void)out_size;
}

// round 7
// speedup vs baseline: 1.0001x; 1.0001x over previous
#include <cuda_runtime.h>
#include <math.h>

// ---------------- problem constants (fixed shapes for this problem) ----------
#define NB   4
#define NN   65536
#define NTOK (NB*NN)        // 262144 tokens
#define CD   256
#define LD   64
#define SD   64
#define AD   16

#define TT     16           // tokens per tile
#define TPB    256          // threads per block
#define TILES  16           // tiles per block
#define TOKBLK (TT*TILES)   // 256 tokens per block
#define GRID_BN (NTOK/TOKBLK) // 1024 blocks
#define BLK_PER_BATCH (NN/TOKBLK) // 256

// ---------------- scratch (no cudaMalloc allowed) ----------------------------
__device__ float g_w[(size_t)NTOK*SD];               // 64 MB softmax assignments
__device__ float g_partA[(size_t)GRID_BN*SD*CD];     // 64 MB per-block slice partials
__device__ float g_partW[GRID_BN*SD];                // wsum partials
__device__ float g_slice[NB*SD*CD];                  // reduced slice tokens (already /wsum)
__device__ float g_st[NB*SD*CD];                     // latent-transition output

// ---------------- helpers ----------------------------------------------------
__device__ __forceinline__ float wsum32(float v) {
#pragma unroll
    for (int o = 16; o; o >>= 1) v += __shfl_xor_sync(0xffffffffu, v, o);
    return v;
}
__device__ __forceinline__ float wmax32(float v) {
#pragma unroll
    for (int o = 16; o; o >>= 1) v = fmaxf(v, __shfl_xor_sync(0xffffffffu, v, o));
    return v;
}
__device__ __forceinline__ float gelu_exact(float x) {
    return 0.5f * x * (1.f + erff(x * 0.70710678118654752440f));
}

// =============================================================================
// Pass A: LN1 -> shared -> feat -> logits -> softmax(w) -> partial scatter
// =============================================================================
__global__ __launch_bounds__(TPB, 2)
void kA(const float* __restrict__ x, const float* __restrict__ geom,
        const float* __restrict__ ln1g, const float* __restrict__ ln1b,
        const float* __restrict__ Wsh, const float* __restrict__ bsh,
        const float* __restrict__ Wf,  const float* __restrict__ bf,
        const float* __restrict__ Wa,  const float* __restrict__ ba)
{
    extern __shared__ float smem[];
    float* h_s    = smem;                 // TT*CD = 4096 (x tile, then h)
    float* sh_s   = h_s   + TT*CD;        // TT*LD = 1024
    float* feat_s = sh_s  + TT*LD;        // TT*CD = 4096
    float* ge_s   = feat_s + TT*CD;       // TT*LD = 1024
    float* w_s    = ge_s  + TT*LD;        // TT*LD = 1024 (logits, then w)

    const int tid  = threadIdx.x;
    const int bid  = blockIdx.x;
    const size_t tokbase = (size_t)bid * TOKBLK;

    float acc_s[SD];
#pragma unroll
    for (int s = 0; s < SD; ++s) acc_s[s] = 0.f;
    float wacc = 0.f;

    const int wid = tid >> 5, lane = tid & 31;
    const int lcol = tid & 63, tq = tid >> 6;   // for 4-output mappings

#pragma unroll 1
    for (int tile = 0; tile < TILES; ++tile) {
        const size_t t0 = tokbase + (size_t)tile * TT;

        // ---- load x tile (float4) and geometry tile ----
        {
            const float4* xg = (const float4*)(x + t0 * CD);
            float4* hv = (float4*)h_s;
#pragma unroll
            for (int q = tid; q < TT*CD/4; q += TPB) hv[q] = xg[q];
            const float4* gg = (const float4*)(geom + t0 * LD);
            float4* gv = (float4*)ge_s;
#pragma unroll
            for (int q = tid; q < TT*LD/4; q += TPB) gv[q] = gg[q];
        }
        __syncthreads();

        // ---- LN1: warp handles 2 tokens ----
        {
#pragma unroll
            for (int t = wid*2; t < wid*2 + 2; ++t) {
                float v[8]; float sum = 0.f;
#pragma unroll
                for (int i = 0; i < 8; ++i) { v[i] = h_s[t*CD + i*32 + lane]; sum += v[i]; }
                sum = wsum32(sum);
                const float mean = sum * (1.f/256.f);
                float sq = 0.f;
#pragma unroll
                for (int i = 0; i < 8; ++i) { float d = v[i]-mean; sq += d*d; }
                sq = wsum32(sq);
                const float rs = rsqrtf(sq * (1.f/256.f) + 1e-5f);
#pragma unroll
                for (int i = 0; i < 8; ++i) {
                    const int c = i*32 + lane;
                    h_s[t*CD + c] = (v[i]-mean)*rs*__ldg(ln1g+c) + __ldg(ln1b+c);
                }
            }
        }
        __syncthreads();

        // ---- shared = h @ Wsh + bsh : thread -> (l=lcol, toks tq,tq+4,tq+8,tq+12)
        // float4 LDS on h rows (broadcast within 64-thread groups)
        {
            float a0 = __ldg(bsh + lcol); float a1 = a0, a2 = a0, a3 = a0;
            const float4* h0 = (const float4*)(h_s + (tq   )*CD);
            const float4* h1 = (const float4*)(h_s + (tq+ 4)*CD);
            const float4* h2 = (const float4*)(h_s + (tq+ 8)*CD);
            const float4* h3 = (const float4*)(h_s + (tq+12)*CD);
#pragma unroll 4
            for (int c4 = 0; c4 < CD/4; ++c4) {
                const int c = c4*4;
                const float w0 = __ldg(Wsh + (c  )*LD + lcol);
                const float w1 = __ldg(Wsh + (c+1)*LD + lcol);
                const float w2 = __ldg(Wsh + (c+2)*LD + lcol);
                const float w3 = __ldg(Wsh + (c+3)*LD + lcol);
                float4 v;
                v = h0[c4]; a0 += v.x*w0 + v.y*w1 + v.z*w2 + v.w*w3;
                v = h1[c4]; a1 += v.x*w0 + v.y*w1 + v.z*w2 + v.w*w3;
                v = h2[c4]; a2 += v.x*w0 + v.y*w1 + v.z*w2 + v.w*w3;
                v = h3[c4]; a3 += v.x*w0 + v.y*w1 + v.z*w2 + v.w*w3;
            }
            sh_s[(tq   )*LD + lcol] = a0;
            sh_s[(tq+ 4)*LD + lcol] = a1;
            sh_s[(tq+ 8)*LD + lcol] = a2;
            sh_s[(tq+12)*LD + lcol] = a3;
        }
        __syncthreads();

        // ---- feat = shared @ Wf + bf : thread -> (c=tid, toks 0..15)
        {
            float fa[TT];
            const float fb = __ldg(bf + tid);
#pragma unroll
            for (int t = 0; t < TT; ++t) fa[t] = fb;
#pragma unroll 2
            for (int l4 = 0; l4 < LD/4; ++l4) {
                const int l = l4*4;
                const float w0 = __ldg(Wf + (l  )*CD + tid);
                const float w1 = __ldg(Wf + (l+1)*CD + tid);
                const float w2 = __ldg(Wf + (l+2)*CD + tid);
                const float w3 = __ldg(Wf + (l+3)*CD + tid);
#pragma unroll
                for (int t = 0; t < TT; ++t) {
                    const float4 sv = ((const float4*)(sh_s + t*LD))[l4];
                    fa[t] += sv.x*w0 + sv.y*w1 + sv.z*w2 + sv.w*w3;
                }
            }
#pragma unroll
            for (int t = 0; t < TT; ++t) feat_s[t*CD + tid] = fa[t];
        }

        // ---- logits = [shared, geom] @ Wa + ba  (reads sh_s/ge_s only; no sync needed)
        {
            float a0 = __ldg(ba + lcol); float a1 = a0, a2 = a0, a3 = a0;
#pragma unroll 4
            for (int k4 = 0; k4 < LD/4; ++k4) {
                const int k = k4*4;
                const float w0 = __ldg(Wa + (k  )*SD + lcol);
                const float w1 = __ldg(Wa + (k+1)*SD + lcol);
                const float w2 = __ldg(Wa + (k+2)*SD + lcol);
                const float w3 = __ldg(Wa + (k+3)*SD + lcol);
                float4 v;
                v = ((const float4*)(sh_s + (tq   )*LD))[k4]; a0 += v.x*w0 + v.y*w1 + v.z*w2 + v.w*w3;
                v = ((const float4*)(sh_s + (tq+ 4)*LD))[k4]; a1 += v.x*w0 + v.y*w1 + v.z*w2 + v.w*w3;
                v = ((const float4*)(sh_s + (tq+ 8)*LD))[k4]; a2 += v.x*w0 + v.y*w1 + v.z*w2 + v.w*w3;
                v = ((const float4*)(sh_s + (tq+12)*LD))[k4]; a3 += v.x*w0 + v.y*w1 + v.z*w2 + v.w*w3;
            }
#pragma unroll 4
            for (int k4 = 0; k4 < LD/4; ++k4) {
                const int k = k4*4;
                const float w0 = __ldg(Wa + (LD+k  )*SD + lcol);
                const float w1 = __ldg(Wa + (LD+k+1)*SD + lcol);
                const float w2 = __ldg(Wa + (LD+k+2)*SD + lcol);
                const float w3 = __ldg(Wa + (LD+k+3)*SD + lcol);
                float4 v;
                v = ((const float4*)(ge_s + (tq   )*LD))[k4]; a0 += v.x*w0 + v.y*w1 + v.z*w2 + v.w*w3;
                v = ((const float4*)(ge_s + (tq+ 4)*LD))[k4]; a1 += v.x*w0 + v.y*w1 + v.z*w2 + v.w*w3;
                v = ((const float4*)(ge_s + (tq+ 8)*LD))[k4]; a2 += v.x*w0 + v.y*w1 + v.z*w2 + v.w*w3;
                v = ((const float4*)(ge_s + (tq+12)*LD))[k4]; a3 += v.x*w0 + v.y*w1 + v.z*w2 + v.w*w3;
            }
            w_s[(tq   )*LD + lcol] = a0;
            w_s[(tq+ 4)*LD + lcol] = a1;
            w_s[(tq+ 8)*LD + lcol] = a2;
            w_s[(tq+12)*LD + lcol] = a3;
        }
        __syncthreads();

        // ---- softmax over S=64, warp per 2 tokens; also write w to global ----
        {
#pragma unroll
            for (int t = wid*2; t < wid*2 + 2; ++t) {
                float v0 = w_s[t*LD + lane], v1 = w_s[t*LD + lane + 32];
                float m = wmax32(fmaxf(v0, v1));
                float e0 = __expf(v0 - m), e1 = __expf(v1 - m);
                float s = wsum32(e0 + e1);
                const float inv = 1.f / s;
                e0 *= inv; e1 *= inv;
                w_s[t*LD + lane]      = e0;
                w_s[t*LD + lane + 32] = e1;
                const size_t tok = t0 + t;
                g_w[tok*SD + lane]      = e0;
                g_w[tok*SD + lane + 32] = e1;
            }
        }
        __syncthreads();

        // ---- scatter: acc[s] += w[t][s] * feat[t][tid], float4 on w row ----
        {
#pragma unroll 1
            for (int t = 0; t < TT; ++t) {
                const float fr = feat_s[t*CD + tid];
                const float4* wv4 = (const float4*)(w_s + t*LD);
#pragma unroll
                for (int s4 = 0; s4 < SD/4; ++s4) {
                    const float4 w = wv4[s4];
                    acc_s[4*s4+0] += w.x * fr;
                    acc_s[4*s4+1] += w.y * fr;
                    acc_s[4*s4+2] += w.z * fr;
                    acc_s[4*s4+3] += w.w * fr;
                }
            }
            if (tid < SD) {
#pragma unroll
                for (int t = 0; t < TT; ++t) wacc += w_s[t*LD + tid];
            }
        }
        __syncthreads();
    }

    // ---- flush per-block partials ----
#pragma unroll
    for (int s = 0; s < SD; ++s)
        g_partA[((size_t)bid*SD + s)*CD + tid] = acc_s[s];
    if (tid < SD) g_partW[bid*SD + tid] = wacc;
}

// =============================================================================
// Reduce partials -> g_slice (already divided by clamp(wsum))
// =============================================================================
__global__ void kR()
{
    const int b = blockIdx.x >> 6;       // batch
    const int s = blockIdx.x & 63;       // slice
    const int tid = threadIdx.x;
    __shared__ float red[TPB];
    red[tid] = g_partW[(b*BLK_PER_BATCH + tid)*SD + s];
    __syncthreads();
#pragma unroll
    for (int o = 128; o; o >>= 1) {
        if (tid < o) red[tid] += red[tid + o];
        __syncthreads();
    }
    const float inv = 1.f / fmaxf(red[0], 1e-6f);
    float acc = 0.f;
#pragma unroll 4
    for (int k = 0; k < BLK_PER_BATCH; ++k)
        acc += g_partA[(((size_t)(b*BLK_PER_BATCH + k))*SD + s)*CD + tid];
    g_slice[((b<<6) + s)*CD + tid] = acc * inv;
}

// =============================================================================
// Pass B: LatentTransition (tiny: 64 rows per batch). One block per batch.
// =============================================================================
__global__ void kB(const float* __restrict__ ltdW, const float* __restrict__ ltdb,
                   const float* __restrict__ dng,  const float* __restrict__ dnb,
                   const float* __restrict__ ancW, const float* __restrict__ ancb,
                   const float* __restrict__ selfW,const float* __restrict__ ctxW,
                   const float* __restrict__ ong,  const float* __restrict__ onb,
                   const float* __restrict__ upW,  const float* __restrict__ upb)
{
    extern __shared__ float sm[];
    float* raw  = sm;            // 4096  (ds raw, later ul)
    float* ls   = raw  + 4096;   // 4096  (ls, later uln)
    float* aw   = ls   + 4096;   // 1024
    float* anc  = aw   + 1024;   // 1024
    float* ctx  = anc  + 1024;   // 4096
    float* asum = ctx  + 4096;   // 16

    const int b = blockIdx.x;
    const int tid = threadIdx.x;
    const float* sl = g_slice + (size_t)b*SD*CD;

    // s1: raw = slice @ lt_down_W + b
    for (int idx = tid; idx < SD*LD; idx += TPB) {
        const int r = idx >> 6, l = idx & 63;
        float acc = __ldg(ltdb + l);
#pragma unroll 4
        for (int c = 0; c < CD; ++c) acc += __ldg(sl + r*CD + c) * __ldg(ltdW + c*LD + l);
        raw[idx] = acc;
    }
    __syncthreads();
    // s2: LN rows -> ls
    if (tid < SD) {
        const int r = tid;
        float m = 0.f;
#pragma unroll
        for (int l = 0; l < LD; ++l) m += raw[r*LD + l];
        m *= (1.f/64.f);
        float v = 0.f;
#pragma unroll
        for (int l = 0; l < LD; ++l) { float d = raw[r*LD + l] - m; v += d*d; }
        const float rs = rsqrtf(v*(1.f/64.f) + 1e-5f);
#pragma unroll
        for (int l = 0; l < LD; ++l)
            ls[r*LD + l] = (raw[r*LD + l] - m)*rs*__ldg(dng+l) + __ldg(dnb+l);
    }
    __syncthreads();
    // s3: anchor logits -> aw
    for (int idx = tid; idx < SD*AD; idx += TPB) {
        const int r = idx >> 4, a = idx & 15;
        float acc = __ldg(ancb + a);
#pragma unroll
        for (int l = 0; l < LD; ++l) acc += ls[r*LD + l] * __ldg(ancW + l*AD + a);
        aw[idx] = acc;
    }
    __syncthreads();
    // s4: softmax rows over A=16
    if (tid < SD) {
        const int r = tid;
        float m = -1e30f;
#pragma unroll
        for (int a = 0; a < AD; ++a) m = fmaxf(m, aw[r*AD + a]);
        float s = 0.f;
#pragma unroll
        for (int a = 0; a < AD; ++a) { float e = __expf(aw[r*AD + a] - m); aw[r*AD + a] = e; s += e; }
        const float inv = 1.f / s;
#pragma unroll
        for (int a = 0; a < AD; ++a) aw[r*AD + a] *= inv;
    }
    __syncthreads();
    // s5: asum
    if (tid < AD) {
        float s = 0.f;
#pragma unroll
        for (int r = 0; r < SD; ++r) s += aw[r*AD + tid];
        asum[tid] = s;
    }
    __syncthreads();
    // s6: anchor
    for (int idx = tid; idx < AD*LD; idx += TPB) {
        const int a = idx >> 6, d = idx & 63;
        float acc = 0.f;
#pragma unroll
        for (int r = 0; r < SD; ++r) acc += aw[r*AD + a] * ls[r*LD + d];
        anc[idx] = acc / fmaxf(asum[a], 1e-6f);
    }
    __syncthreads();
    // s7: ctx
    for (int idx = tid; idx < SD*LD; idx += TPB) {
        const int r = idx >> 6, d = idx & 63;
        float acc = 0.f;
#pragma unroll
        for (int a = 0; a < AD; ++a) acc += aw[r*AD + a] * anc[a*LD + d];
        ctx[idx] = acc;
    }
    __syncthreads();
    // s8: ul = ls + gelu(ls@selfW + ctx@ctxW)  -> raw
    for (int idx = tid; idx < SD*LD; idx += TPB) {
        const int r = idx >> 6, d = idx & 63;
        float acc = 0.f;
#pragma unroll
        for (int l = 0; l < LD; ++l) acc += ls[r*LD + l] * __ldg(selfW + l*LD + d);
#pragma unroll
        for (int l = 0; l < LD; ++l) acc += ctx[r*LD + l] * __ldg(ctxW + l*LD + d);
        raw[idx] = ls[idx] + gelu_exact(acc);
    }
    __syncthreads();
    // s9: LN(ul) -> ls (uln)
    if (tid < SD) {
        const int r = tid;
        float m = 0.f;
#pragma unroll
        for (int l = 0; l < LD; ++l) m += raw[r*LD + l];
        m *= (1.f/64.f);
        float v = 0.f;
#pragma unroll
        for (int l = 0; l < LD; ++l) { float d = raw[r*LD + l] - m; v += d*d; }
        const float rs = rsqrtf(v*(1.f/64.f) + 1e-5f);
#pragma unroll
        for (int l = 0; l < LD; ++l)
            ls[r*LD + l] = (raw[r*LD + l] - m)*rs*__ldg(ong+l) + __ldg(onb+l);
    }
    __syncthreads();
    // s10: st = uln @ upW + upb
    for (int idx = tid; idx < SD*CD; idx += TPB) {
        const int r = idx >> 8, c = idx & 255;
        float acc = __ldg(upb + c);
#pragma unroll
        for (int l = 0; l < LD; ++l) acc += ls[r*LD + l] * __ldg(upW + l*CD + c);
        g_st[(size_t)b*SD*CD + idx] = acc;
    }
}

// =============================================================================
// Pass C: reader + residual, LN2, ChannelMixer GLU + residual -> out
// =============================================================================
__global__ __launch_bounds__(TPB, 2)
void kC(const float* __restrict__ x, float* __restrict__ out,
        const float* __restrict__ ln2g, const float* __restrict__ ln2b,
        const float* __restrict__ cinW, const float* __restrict__ cinb,
        const float* __restrict__ coutW,const float* __restrict__ coutb)
{
    extern __shared__ float smem[];
    float* st_s  = smem;                  // SD*CD = 16384
    float* x1_s  = st_s + SD*CD;          // TT*CD = 4096
    float* y_s   = x1_s + TT*CD;          // TT*CD = 4096
    float* vg_s  = y_s  + TT*CD;          // TT*128 = 2048
    float* wa_s  = vg_s + TT*2*LD;        // TT*LD = 1024 (w, then act)

    const int tid = threadIdx.x;
    const int bid = blockIdx.x;
    const size_t tokbase = (size_t)bid * TOKBLK;
    const int b = (int)(tokbase / NN);
    const int wid = tid >> 5, lane = tid & 31;

    // cache st for this batch
    {
        const float4* sg = (const float4*)(g_st + (size_t)b*SD*CD);
        float4* sv = (float4*)st_s;
#pragma unroll
        for (int q = tid; q < SD*CD/4; q += TPB) sv[q] = sg[q];
    }
    __syncthreads();

#pragma unroll 1
    for (int tile = 0; tile < TILES; ++tile) {
        const size_t t0 = tokbase + (size_t)tile * TT;

        // load x tile and w tile
        {
            const float4* xg = (const float4*)(x + t0 * CD);
            float4* xv = (float4*)x1_s;
#pragma unroll
            for (int q = tid; q < TT*CD/4; q += TPB) xv[q] = xg[q];
            const float4* wg = (const float4*)(g_w + t0 * SD);
            float4* wv = (float4*)wa_s;
#pragma unroll
            for (int q = tid; q < TT*SD/4; q += TPB) wv[q] = wg[q];
        }
        __syncthreads();

        // x1 = x + w @ st : thread owns column c=tid, all 16 tokens; float4 on w rows
        {
            float a1[TT];
#pragma unroll
            for (int t = 0; t < TT; ++t) a1[t] = x1_s[t*CD + tid];
#pragma unroll 2
            for (int s4 = 0; s4 < SD/4; ++s4) {
                const int s = s4*4;
                const float st0 = st_s[(s  )*CD + tid];
                const float st1 = st_s[(s+1)*CD + tid];
                const float st2 = st_s[(s+2)*CD + tid];
                const float st3 = st_s[(s+3)*CD + tid];
#pragma unroll
                for (int t = 0; t < TT; ++t) {
                    const float4 w = ((const float4*)(wa_s + t*SD))[s4];
                    a1[t] += w.x*st0 + w.y*st1 + w.z*st2 + w.w*st3;
                }
            }
#pragma unroll
            for (int t = 0; t < TT; ++t) x1_s[t*CD + tid] = a1[t];
        }
        __syncthreads();

        // LN2: warp per 2 tokens, x1_s -> y_s
        {
#pragma unroll
            for (int t = wid*2; t < wid*2 + 2; ++t) {
                float v[8]; float sum = 0.f;
#pragma unroll
                for (int i = 0; i < 8; ++i) { v[i] = x1_s[t*CD + i*32 + lane]; sum += v[i]; }
                sum = wsum32(sum);
                const float mean = sum * (1.f/256.f);
                float sq = 0.f;
#pragma unroll
                for (int i = 0; i < 8; ++i) { float d = v[i]-mean; sq += d*d; }
                sq = wsum32(sq);
                const float rs = rsqrtf(sq * (1.f/256.f) + 1e-5f);
#pragma unroll
                for (int i = 0; i < 8; ++i) {
                    const int c = i*32 + lane;
                    y_s[t*CD + c] = (v[i]-mean)*rs*__ldg(ln2g+c) + __ldg(ln2b+c);
                }
            }
        }
        __syncthreads();

        // vg = y @ cm_in_W + b : thread -> (j = tid&127, toks tt2, tt2+2, ..., tt2+14)
        {
            const int j = tid & 127, tt2 = tid >> 7;  // tt2 in {0,1}
            float acc[8];
            const float cb = __ldg(cinb + j);
#pragma unroll
            for (int k = 0; k < 8; ++k) acc[k] = cb;
#pragma unroll 2
            for (int c4 = 0; c4 < CD/4; ++c4) {
                const int c = c4*4;
                const float w0 = __ldg(cinW + (c  )*128 + j);
                const float w1 = __ldg(cinW + (c+1)*128 + j);
                const float w2 = __ldg(cinW + (c+2)*128 + j);
                const float w3 = __ldg(cinW + (c+3)*128 + j);
#pragma unroll
                for (int k = 0; k < 8; ++k) {
                    const float4 yv = ((const float4*)(y_s + (tt2 + 2*k)*CD))[c4];
                    acc[k] += yv.x*w0 + yv.y*w1 + yv.z*w2 + yv.w*w3;
                }
            }
#pragma unroll
            for (int k = 0; k < 8; ++k) vg_s[(tt2 + 2*k)*128 + j] = acc[k];
        }
        __syncthreads();

        // act = gelu(v) * sigmoid(g) -> wa_s
        for (int idx = tid; idx < TT*LD; idx += TPB) {
            const int t = idx >> 6, l = idx & 63;
            const float v = vg_s[t*128 + l];
            const float g = vg_s[t*128 + 64 + l];
            wa_s[idx] = gelu_exact(v) * (1.f / (1.f + __expf(-g)));
        }
        __syncthreads();

        // out = x1 + act @ cm_out_W + cm_out_b : thread owns column c=tid; float4 on act rows
        {
            float a2[TT];
            const float bo = __ldg(coutb + tid);
#pragma unroll
            for (int t = 0; t < TT; ++t) a2[t] = x1_s[t*CD + tid] + bo;
#pragma unroll 2
            for (int l4 = 0; l4 < LD/4; ++l4) {
                const int l = l4*4;
                const float w0 = __ldg(coutW + (l  )*CD + tid);
                const float w1 = __ldg(coutW + (l+1)*CD + tid);
                const float w2 = __ldg(coutW + (l+2)*CD + tid);
                const float w3 = __ldg(coutW + (l+3)*CD + tid);
#pragma unroll
                for (int t = 0; t < TT; ++t) {
                    const float4 av = ((const float4*)(wa_s + t*LD))[l4];
                    a2[t] += av.x*w0 + av.y*w1 + av.z*w2 + av.w*w3;
                }
            }
#pragma unroll
            for (int t = 0; t < TT; ++t) out[(t0 + t)*CD + tid] = a2[t];
        }
        __syncthreads();
    }
}

// =============================================================================
extern "C" void kernel_launch(void* const* d_in, const int* in_sizes, int n_in,
                              void* d_out, int out_size)
{
    const float* x     = (const float*)d_in[0];
    const float* geom  = (const float*)d_in[1];
    const float* ln1g  = (const float*)d_in[2];
    const float* ln1b  = (const float*)d_in[3];
    const float* Wsh   = (const float*)d_in[4];
    const float* bsh   = (const float*)d_in[5];
    const float* Wf    = (const float*)d_in[6];
    const float* bf    = (const float*)d_in[7];
    const float* Wa    = (const float*)d_in[8];
    const float* ba    = (const float*)d_in[9];
    const float* ltdW  = (const float*)d_in[10];
    const float* ltdb  = (const float*)d_in[11];
    const float* dng   = (const float*)d_in[12];
    const float* dnb   = (const float*)d_in[13];
    const float* ancW  = (const float*)d_in[14];
    const float* ancb  = (const float*)d_in[15];
    const float* selfW = (const float*)d_in[16];
    const float* ctxW  = (const float*)d_in[17];
    const float* ong   = (const float*)d_in[18];
    const float* onb   = (const float*)d_in[19];
    const float* upW   = (const float*)d_in[20];
    const float* upb   = (const float*)d_in[21];
    const float* ln2g  = (const float*)d_in[22];
    const float* ln2b  = (const float*)d_in[23];
    const float* cinW  = (const float*)d_in[24];
    const float* cinb  = (const float*)d_in[25];
    const float* coutW = (const float*)d_in[26];
    const float* coutb = (const float*)d_in[27];
    float* out = (float*)d_out;

    const int smemA = (TT*CD + TT*LD + TT*CD + TT*LD + TT*LD) * 4;           // 45056
    const int smemB = (4096 + 4096 + 1024 + 1024 + 4096 + 16) * 4;           // 57408
    const int smemC = (SD*CD + TT*CD + TT*CD + TT*2*LD + TT*LD) * 4;         // 110592

    cudaFuncSetAttribute(kA, cudaFuncAttributeMaxDynamicSharedMemorySize, smemA);
    cudaFuncSetAttribute(kB, cudaFuncAttributeMaxDynamicSharedMemorySize, smemB);
    cudaFuncSetAttribute(kC, cudaFuncAttributeMaxDynamicSharedMemorySize, smemC);

    kA<<<GRID_BN, TPB, smemA>>>(x, geom, ln1g, ln1b, Wsh, bsh, Wf, bf, Wa, ba);
    kR<<<NB*SD, TPB>>>();
    kB<<<NB, TPB, smemB>>>(ltdW, ltdb, dng, dnb, ancW, ancb, selfW, ctxW, ong, onb, upW, upb);
    kC<<<GRID_BN, TPB, smemC>>>(x, out, ln2g, ln2b, cinW, cinb, coutW, coutb);

    (void)in_sizes; (void)n_in; (void)out_size;
}

// round 13
// speedup vs baseline: 2.1321x; 2.1319x over previous
#include <cuda_runtime.h>
#include <math.h>

#define NB   4
#define NN   65536
#define NTOK (NB*NN)
#define CD   256
#define LD   64
#define SD   64
#define AD   16

#define TTA    32
#define TPB    256
#define TPBW   512
#define ITERS  8
#define TOKBLK 256
#define GRID_BN (NTOK/TOKBLK)
#define BLK_PER_BATCH (NN/TOKBLK)

#define S_H  264
#define S_L  72
#define S_VG 136

__device__ float g_w[(size_t)NTOK*SD];
__device__ float g_partA[(size_t)GRID_BN*SD*CD];
__device__ float g_partW[GRID_BN*SD];
__device__ float g_slice[NB*SD*CD];
__device__ float g_WshP[256*64];
__device__ float g_WfP [64*256];
__device__ float g_WaP [128*64];
__device__ float g_cinP[256*128];
__device__ float g_coutP[64*256];
__device__ float g_stP [NB*64*256];

__device__ __forceinline__ float wsum32(float v) {
#pragma unroll
    for (int o = 16; o; o >>= 1) v += __shfl_xor_sync(0xffffffffu, v, o);
    return v;
}
__device__ __forceinline__ float wmax32(float v) {
#pragma unroll
    for (int o = 16; o; o >>= 1) v = fmaxf(v, __shfl_xor_sync(0xffffffffu, v, o));
    return v;
}
__device__ __forceinline__ float gelu_exact(float x) {
    return 0.5f * x * (1.f + erff(x * 0.70710678118654752440f));
}
__device__ __forceinline__ float f2tf(float x) {
    unsigned u; asm("cvt.rna.tf32.f32 %0, %1;" : "=r"(u) : "f"(x));
    return __uint_as_float(u);
}
__device__ __forceinline__ void mma8(float* c, const unsigned* a, const unsigned* b) {
    asm volatile(
        "mma.sync.aligned.m16n8k8.row.col.f32.tf32.tf32.f32 "
        "{%0,%1,%2,%3}, {%4,%5,%6,%7}, {%8,%9}, {%0,%1,%2,%3};\n"
        : "+f"(c[0]), "+f"(c[1]), "+f"(c[2]), "+f"(c[3])
        : "r"(a[0]), "r"(a[1]), "r"(a[2]), "r"(a[3]), "r"(b[0]), "r"(b[1]));
}
__device__ __forceinline__ void lda(unsigned* a, const float* smb, int stride,
                                    int m0, int k0, int g, int tg) {
    a[0] = __float_as_uint(smb[(m0+g  )*stride + k0 + tg    ]);
    a[1] = __float_as_uint(smb[(m0+g+8)*stride + k0 + tg    ]);
    a[2] = __float_as_uint(smb[(m0+g  )*stride + k0 + tg + 4]);
    a[3] = __float_as_uint(smb[(m0+g+8)*stride + k0 + tg + 4]);
}
__device__ __forceinline__ void ldb(unsigned* b, const float* p) {
    float2 v = *(const float2*)p;
    b[0] = __float_as_uint(v.x); b[1] = __float_as_uint(v.y);
}

// pack W[K][N] -> tf32 B-fragment order: addr=((nb*KB+kb)*32+lane)*2+reg
__global__ void kPack(const float* __restrict__ src, int which, int K, int N) {
    float* dst = (which==0) ? g_WshP : (which==1) ? g_WfP :
                 (which==2) ? g_WaP  : (which==3) ? g_cinP : g_coutP;
    const int KB = K >> 3;
    const int total = K * N;
    for (int p = blockIdx.x*blockDim.x + threadIdx.x; p < total; p += gridDim.x*blockDim.x) {
        int reg = p & 1, lane2 = (p >> 1) & 31, rest = p >> 6;
        int kb = rest % KB, nb = rest / KB;
        int k = kb*8 + (lane2 & 3) + 4*reg;
        int n = nb*8 + (lane2 >> 2);
        dst[p] = f2tf(src[k*N + n]);
    }
}

__global__ __launch_bounds__(TPBW, 1)
void kA(const float* __restrict__ x, const float* __restrict__ geom,
        const float* __restrict__ ln1g, const float* __restrict__ ln1b,
        const float* __restrict__ bsh, const float* __restrict__ bf,
        const float* __restrict__ ba)
{
    extern __shared__ float sm[];
    float* h_s    = sm;
    float* sh_s   = h_s    + 32*S_H;
    float* feat_s = sh_s   + 32*S_L;
    float* ge_s   = feat_s + 32*S_H;
    float* w_s    = ge_s   + 32*S_L;
    float* WshS   = w_s    + 32*S_L;
    float* WaS    = WshS   + 16384;

    const int tid = threadIdx.x, wid = tid >> 5, lane = tid & 31;
    const int g = lane >> 2, tg = lane & 3;
    const int bid = blockIdx.x;
    const size_t tokbase = (size_t)bid * TOKBLK;

    for (int q = tid; q < 4096; q += TPBW) ((float4*)WshS)[q] = ((const float4*)g_WshP)[q];
    for (int q = tid; q < 2048; q += TPBW) ((float4*)WaS)[q]  = ((const float4*)g_WaP)[q];

    float sc[32];
#pragma unroll
    for (int i = 0; i < 32; ++i) sc[i] = 0.f;
    float wacc = 0.f;

    const int m0  = (wid & 1) * 16;
    const int nbw = wid >> 1;

#pragma unroll 1
    for (int iter = 0; iter < ITERS; ++iter) {
        const size_t t0 = tokbase + (size_t)iter * TTA;
        {
            const float4* xg = (const float4*)(x + t0 * CD);
            for (int q = tid; q < 2048; q += TPBW) {
                int r = q >> 6, c4 = q & 63;
                ((float4*)h_s)[r*66 + c4] = xg[q];
            }
            int r = tid >> 4, c4 = tid & 15;
            float4 v = ((const float4*)(geom + t0 * LD))[tid];
            v.x = f2tf(v.x); v.y = f2tf(v.y); v.z = f2tf(v.z); v.w = f2tf(v.w);
            ((float4*)ge_s)[r*18 + c4] = v;
        }
        __syncthreads();

#pragma unroll
        for (int tt = 0; tt < 2; ++tt) {
            int t = wid*2 + tt;
            float v[8]; float s = 0.f;
#pragma unroll
            for (int i = 0; i < 8; ++i) { v[i] = h_s[t*S_H + i*32 + lane]; s += v[i]; }
            s = wsum32(s); const float mean = s * (1.f/256.f);
            float sq = 0.f;
#pragma unroll
            for (int i = 0; i < 8; ++i) { float d = v[i]-mean; sq += d*d; }
            sq = wsum32(sq);
            const float rs = rsqrtf(sq * (1.f/256.f) + 1e-5f);
#pragma unroll
            for (int i = 0; i < 8; ++i) {
                int c = i*32 + lane;
                h_s[t*S_H + c] = f2tf((v[i]-mean)*rs*__ldg(ln1g+c) + __ldg(ln1b+c));
            }
        }
        __syncthreads();

        unsigned a[4], b[2];
        { // shared = h @ Wsh + bsh (M32 N64 K256)
            float c1[4] = {0.f,0.f,0.f,0.f};
#pragma unroll 4
            for (int kb = 0; kb < 32; ++kb) {
                lda(a, h_s, S_H, m0, kb*8, g, tg);
                ldb(b, WshS + ((nbw*32 + kb)*32 + lane)*2);
                mma8(c1, a, b);
            }
            int col = nbw*8 + 2*tg;
            float b0 = __ldg(bsh+col), b1 = __ldg(bsh+col+1);
            *(float2*)(sh_s + (m0+g  )*S_L + col) = make_float2(f2tf(c1[0]+b0), f2tf(c1[1]+b1));
            *(float2*)(sh_s + (m0+g+8)*S_L + col) = make_float2(f2tf(c1[2]+b0), f2tf(c1[3]+b1));
        }
        __syncthreads();

        { // feat = shared @ Wf + bf (M32 N256 K64)
            float c2[16];
#pragma unroll
            for (int i = 0; i < 16; ++i) c2[i] = 0.f;
#pragma unroll
            for (int kb = 0; kb < 8; ++kb) {
                lda(a, sh_s, S_L, m0, kb*8, g, tg);
#pragma unroll
                for (int j = 0; j < 4; ++j) {
                    ldb(b, g_WfP + (((nbw*4+j)*8 + kb)*32 + lane)*2);
                    mma8(c2 + j*4, a, b);
                }
            }
#pragma unroll
            for (int j = 0; j < 4; ++j) {
                int col = (nbw*4+j)*8 + 2*tg;
                float b0 = __ldg(bf+col), b1 = __ldg(bf+col+1);
                *(float2*)(feat_s + (m0+g  )*S_H + col) = make_float2(f2tf(c2[j*4+0]+b0), f2tf(c2[j*4+1]+b1));
                *(float2*)(feat_s + (m0+g+8)*S_H + col) = make_float2(f2tf(c2[j*4+2]+b0), f2tf(c2[j*4+3]+b1));
            }
        }

        { // logits = [shared|geom] @ Wa + ba (M32 N64 K128), fp32 out
            float c3[4] = {0.f,0.f,0.f,0.f};
#pragma unroll
            for (int kb = 0; kb < 16; ++kb) {
                if (kb < 8) lda(a, sh_s, S_L, m0, kb*8, g, tg);
                else        lda(a, ge_s, S_L, m0, (kb-8)*8, g, tg);
                ldb(b, WaS + ((nbw*16 + kb)*32 + lane)*2);
                mma8(c3, a, b);
            }
            int col = nbw*8 + 2*tg;
            float b0 = __ldg(ba+col), b1 = __ldg(ba+col+1);
            *(float2*)(w_s + (m0+g  )*S_L + col) = make_float2(c3[0]+b0, c3[1]+b1);
            *(float2*)(w_s + (m0+g+8)*S_L + col) = make_float2(c3[2]+b0, c3[3]+b1);
        }
        __syncthreads();

#pragma unroll
        for (int tt = 0; tt < 2; ++tt) { // softmax S=64
            int t = wid*2 + tt;
            float v0 = w_s[t*S_L + lane], v1 = w_s[t*S_L + lane + 32];
            float m = wmax32(fmaxf(v0, v1));
            float e0 = __expf(v0 - m), e1 = __expf(v1 - m);
            float ssum = wsum32(e0 + e1);
            float inv = 1.f / ssum; e0 *= inv; e1 *= inv;
            w_s[t*S_L + lane]      = e0;
            w_s[t*S_L + lane + 32] = e1;
            g_w[(t0 + t)*SD + lane]      = e0;
            g_w[(t0 + t)*SD + lane + 32] = e1;
        }
        __syncthreads();

        if (tid < SD) {
#pragma unroll
            for (int t = 0; t < TTA; ++t) wacc += w_s[t*S_L + tid];
        }

        // scatter: D(64x256) += w^T(64x32) @ feat(32x256)
#pragma unroll
        for (int ks = 0; ks < 4; ++ks) {
            unsigned am[2][4];
#pragma unroll
            for (int i = 0; i < 2; ++i) {
                int mb = (wid >> 3)*2 + i;
                am[i][0] = __float_as_uint(f2tf(w_s[(ks*8+tg  )*S_L + mb*16 + g  ]));
                am[i][1] = __float_as_uint(f2tf(w_s[(ks*8+tg  )*S_L + mb*16 + g+8]));
                am[i][2] = __float_as_uint(f2tf(w_s[(ks*8+tg+4)*S_L + mb*16 + g  ]));
                am[i][3] = __float_as_uint(f2tf(w_s[(ks*8+tg+4)*S_L + mb*16 + g+8]));
            }
#pragma unroll
            for (int j = 0; j < 4; ++j) {
                int nb = (wid & 7)*4 + j;
                b[0] = __float_as_uint(feat_s[(ks*8+tg  )*S_H + nb*8 + g]);
                b[1] = __float_as_uint(feat_s[(ks*8+tg+4)*S_H + nb*8 + g]);
                mma8(sc + j*4,      am[0], b);
                mma8(sc + 16 + j*4, am[1], b);
            }
        }
        __syncthreads();
    }

#pragma unroll
    for (int i = 0; i < 2; ++i) {
#pragma unroll
        for (int j = 0; j < 4; ++j) {
            int mb = (wid >> 3)*2 + i, nb = (wid & 7)*4 + j;
            int s0 = mb*16 + g, c0 = nb*8 + 2*tg;
            float* dst = g_partA + (size_t)bid * SD * CD;
            const float* s = sc + i*16 + j*4;
            *(float2*)(dst + (size_t)s0*CD + c0)     = make_float2(s[0], s[1]);
            *(float2*)(dst + (size_t)(s0+8)*CD + c0) = make_float2(s[2], s[3]);
        }
    }
    if (tid < SD) g_partW[bid*SD + tid] = wacc;
}

__global__ void kR()
{
    const int b = blockIdx.x >> 6;
    const int s = blockIdx.x & 63;
    const int tid = threadIdx.x;
    __shared__ float red[TPB];
    red[tid] = g_partW[(b*BLK_PER_BATCH + tid)*SD + s];
    __syncthreads();
#pragma unroll
    for (int o = 128; o; o >>= 1) {
        if (tid < o) red[tid] += red[tid + o];
        __syncthreads();
    }
    const float inv = 1.f / fmaxf(red[0], 1e-6f);
    float acc = 0.f;
#pragma unroll 4
    for (int k = 0; k < BLK_PER_BATCH; ++k)
        acc += g_partA[(((size_t)(b*BLK_PER_BATCH + k))*SD + s)*CD + tid];
    g_slice[((b<<6) + s)*CD + tid] = acc * inv;
}

__global__ void kB(const float* __restrict__ ltdW, const float* __restrict__ ltdb,
                   const float* __restrict__ dng,  const float* __restrict__ dnb,
                   const float* __restrict__ ancW, const float* __restrict__ ancb,
                   const float* __restrict__ selfW,const float* __restrict__ ctxW,
                   const float* __restrict__ ong,  const float* __restrict__ onb,
                   const float* __restrict__ upW,  const float* __restrict__ upb)
{
    extern __shared__ float smB[];
    float* raw  = smB;
    float* ls   = raw  + 4096;
    float* aw   = ls   + 4096;
    float* anc  = aw   + 1024;
    float* ctx  = anc  + 1024;
    float* asum = ctx  + 4096;

    const int b = blockIdx.x;
    const int tid = threadIdx.x;
    const float* sl = g_slice + (size_t)b*SD*CD;

    for (int idx = tid; idx < SD*LD; idx += TPB) {
        const int r = idx >> 6, l = idx & 63;
        float acc = __ldg(ltdb + l);
#pragma unroll 4
        for (int c = 0; c < CD; ++c) acc += __ldg(sl + r*CD + c) * __ldg(ltdW + c*LD + l);
        raw[idx] = acc;
    }
    __syncthreads();
    if (tid < SD) {
        const int r = tid;
        float m = 0.f;
#pragma unroll
        for (int l = 0; l < LD; ++l) m += raw[r*LD + l];
        m *= (1.f/64.f);
        float v = 0.f;
#pragma unroll
        for (int l = 0; l < LD; ++l) { float d = raw[r*LD + l] - m; v += d*d; }
        const float rs = rsqrtf(v*(1.f/64.f) + 1e-5f);
#pragma unroll
        for (int l = 0; l < LD; ++l)
            ls[r*LD + l] = (raw[r*LD + l] - m)*rs*__ldg(dng+l) + __ldg(dnb+l);
    }
    __syncthreads();
    for (int idx = tid; idx < SD*AD; idx += TPB) {
        const int r = idx >> 4, a = idx & 15;
        float acc = __ldg(ancb + a);
#pragma unroll
        for (int l = 0; l < LD; ++l) acc += ls[r*LD + l] * __ldg(ancW + l*AD + a);
        aw[idx] = acc;
    }
    __syncthreads();
    if (tid < SD) {
        const int r = tid;
        float m = -1e30f;
#pragma unroll
        for (int a = 0; a < AD; ++a) m = fmaxf(m, aw[r*AD + a]);
        float s = 0.f;
#pragma unroll
        for (int a = 0; a < AD; ++a) { float e = __expf(aw[r*AD + a] - m); aw[r*AD + a] = e; s += e; }
        const float inv = 1.f / s;
#pragma unroll
        for (int a = 0; a < AD; ++a) aw[r*AD + a] *= inv;
    }
    __syncthreads();
    if (tid < AD) {
        float s = 0.f;
#pragma unroll
        for (int r = 0; r < SD; ++r) s += aw[r*AD + tid];
        asum[tid] = s;
    }
    __syncthreads();
    for (int idx = tid; idx < AD*LD; idx += TPB) {
        const int a = idx >> 6, d = idx & 63;
        float acc = 0.f;
#pragma unroll
        for (int r = 0; r < SD; ++r) acc += aw[r*AD + a] * ls[r*LD + d];
        anc[idx] = acc / fmaxf(asum[a], 1e-6f);
    }
    __syncthreads();
    for (int idx = tid; idx < SD*LD; idx += TPB) {
        const int r = idx >> 6, d = idx & 63;
        float acc = 0.f;
#pragma unroll
        for (int a = 0; a < AD; ++a) acc += aw[r*AD + a] * anc[a*LD + d];
        ctx[idx] = acc;
    }
    __syncthreads();
    for (int idx = tid; idx < SD*LD; idx += TPB) {
        const int r = idx >> 6, d = idx & 63;
        float acc = 0.f;
#pragma unroll
        for (int l = 0; l < LD; ++l) acc += ls[r*LD + l] * __ldg(selfW + l*LD + d);
#pragma unroll
        for (int l = 0; l < LD; ++l) acc += ctx[r*LD + l] * __ldg(ctxW + l*LD + d);
        raw[idx] = ls[idx] + gelu_exact(acc);
    }
    __syncthreads();
    if (tid < SD) {
        const int r = tid;
        float m = 0.f;
#pragma unroll
        for (int l = 0; l < LD; ++l) m += raw[r*LD + l];
        m *= (1.f/64.f);
        float v = 0.f;
#pragma unroll
        for (int l = 0; l < LD; ++l) { float d = raw[r*LD + l] - m; v += d*d; }
        const float rs = rsqrtf(v*(1.f/64.f) + 1e-5f);
#pragma unroll
        for (int l = 0; l < LD; ++l)
            ls[r*LD + l] = (raw[r*LD + l] - m)*rs*__ldg(ong+l) + __ldg(onb+l);
    }
    __syncthreads();
    // st packed tf32 B-frag per batch (KB=8)
    for (int idx = tid; idx < SD*CD; idx += TPB) {
        const int r = idx >> 8, c = idx & 255;
        float acc = __ldg(upb + c);
#pragma unroll
        for (int l = 0; l < LD; ++l) acc += ls[r*LD + l] * __ldg(upW + l*CD + c);
        const int nb = c >> 3, kb = r >> 3;
        const int lane2 = ((c & 7) << 2) | (r & 3);
        const int reg = (r >> 2) & 1;
        g_stP[(((size_t)(b*32 + nb)*8 + kb)*32 + lane2)*2 + reg] = f2tf(acc);
    }
}

__global__ __launch_bounds__(TPBW, 1)
void kC(const float* __restrict__ x, float* __restrict__ out,
        const float* __restrict__ ln2g, const float* __restrict__ ln2b,
        const float* __restrict__ cinb, const float* __restrict__ coutb)
{
    extern __shared__ float sm[];
    float* x1_s = sm;
    float* y_s  = x1_s + 32*S_H;
    float* w_s  = y_s  + 32*S_H;
    float* vg_s = w_s  + 32*S_L;
    float* stS  = vg_s + 32*S_VG;
    float* coS  = stS  + 16384;

    const int tid = threadIdx.x, wid = tid >> 5, lane = tid & 31;
    const int g = lane >> 2, tg = lane & 3;
    const int bid = blockIdx.x;
    const size_t tokbase = (size_t)bid * TOKBLK;
    const int bat = bid >> 8;

    for (int q = tid; q < 4096; q += TPBW)
        ((float4*)stS)[q] = ((const float4*)(g_stP + (size_t)bat*16384))[q];
    for (int q = tid; q < 4096; q += TPBW)
        ((float4*)coS)[q] = ((const float4*)g_coutP)[q];

    const int m0  = (wid & 1) * 16;
    const int nbw = wid >> 1;

#pragma unroll 1
    for (int iter = 0; iter < ITERS; ++iter) {
        const size_t t0 = tokbase + (size_t)iter * TTA;
        {
            const float4* xg = (const float4*)(x + t0 * CD);
            for (int q = tid; q < 2048; q += TPBW) {
                int r = q >> 6, c4 = q & 63;
                ((float4*)x1_s)[r*66 + c4] = xg[q];
            }
            int r = tid >> 4, c4 = tid & 15;
            float4 v = ((const float4*)(g_w + t0 * SD))[tid];
            v.x = f2tf(v.x); v.y = f2tf(v.y); v.z = f2tf(v.z); v.w = f2tf(v.w);
            ((float4*)w_s)[r*18 + c4] = v;
        }
        __syncthreads();

        unsigned a[4], b[2];
        { // x1 = x + w(32x64) @ st(64x256)
            float cr[16];
#pragma unroll
            for (int i = 0; i < 16; ++i) cr[i] = 0.f;
#pragma unroll
            for (int kb = 0; kb < 8; ++kb) {
                lda(a, w_s, S_L, m0, kb*8, g, tg);
#pragma unroll
                for (int j = 0; j < 4; ++j) {
                    ldb(b, stS + (((nbw*4+j)*8 + kb)*32 + lane)*2);
                    mma8(cr + j*4, a, b);
                }
            }
#pragma unroll
            for (int j = 0; j < 4; ++j) {
                int col = (nbw*4+j)*8 + 2*tg;
                float2* p0 = (float2*)(x1_s + (m0+g  )*S_H + col);
                float2* p1 = (float2*)(x1_s + (m0+g+8)*S_H + col);
                float2 v0 = *p0, v1 = *p1;
                v0.x += cr[j*4+0]; v0.y += cr[j*4+1];
                v1.x += cr[j*4+2]; v1.y += cr[j*4+3];
                *p0 = v0; *p1 = v1;
            }
        }
        __syncthreads();

#pragma unroll
        for (int tt = 0; tt < 2; ++tt) { // LN2 -> y_s tf32
            int t = wid*2 + tt;
            float v[8]; float s = 0.f;
#pragma unroll
            for (int i = 0; i < 8; ++i) { v[i] = x1_s[t*S_H + i*32 + lane]; s += v[i]; }
            s = wsum32(s); const float mean = s * (1.f/256.f);
            float sq = 0.f;
#pragma unroll
            for (int i = 0; i < 8; ++i) { float d = v[i]-mean; sq += d*d; }
            sq = wsum32(sq);
            const float rs = rsqrtf(sq * (1.f/256.f) + 1e-5f);
#pragma unroll
            for (int i = 0; i < 8; ++i) {
                int c = i*32 + lane;
                y_s[t*S_H + c] = f2tf((v[i]-mean)*rs*__ldg(ln2g+c) + __ldg(ln2b+c));
            }
        }
        __syncthreads();

        { // vg = y(32x256) @ cm_in(256x128) + b
            float ci[8];
#pragma unroll
            for (int i = 0; i < 8; ++i) ci[i] = 0.f;
#pragma unroll 4
            for (int kb = 0; kb < 32; ++kb) {
                lda(a, y_s, S_H, m0, kb*8, g, tg);
#pragma unroll
                for (int j = 0; j < 2; ++j) {
                    ldb(b, g_cinP + (((nbw*2+j)*32 + kb)*32 + lane)*2);
                    mma8(ci + j*4, a, b);
                }
            }
#pragma unroll
            for (int j = 0; j < 2; ++j) {
                int col = (nbw*2+j)*8 + 2*tg;
                float b0 = __ldg(cinb+col), b1 = __ldg(cinb+col+1);
                *(float2*)(vg_s + (m0+g  )*S_VG + col) = make_float2(ci[j*4+0]+b0, ci[j*4+1]+b1);
                *(float2*)(vg_s + (m0+g+8)*S_VG + col) = make_float2(ci[j*4+2]+b0, ci[j*4+3]+b1);
            }
        }
        __syncthreads();

        for (int q = tid; q < 2048; q += TPBW) { // GLU act, tf32
            int t = q >> 6, l = q & 63;
            float v = vg_s[t*S_VG + l], gg = vg_s[t*S_VG + 64 + l];
            vg_s[t*S_VG + l] = f2tf(gelu_exact(v) * (1.f / (1.f + __expf(-gg))));
        }
        __syncthreads();

        { // out = x1 + act(32x64) @ cm_out(64x256) + b  -> y_s
            float co[16];
#pragma unroll
            for (int i = 0; i < 16; ++i) co[i] = 0.f;
#pragma unroll
            for (int kb = 0; kb < 8; ++kb) {
                lda(a, vg_s, S_VG, m0, kb*8, g, tg);
#pragma unroll
                for (int j = 0; j < 4; ++j) {
                    ldb(b, coS + (((nbw*4+j)*8 + kb)*32 + lane)*2);
                    mma8(co + j*4, a, b);
                }
            }
#pragma unroll
            for (int j = 0; j < 4; ++j) {
                int col = (nbw*4+j)*8 + 2*tg;
                float b0 = __ldg(coutb+col), b1 = __ldg(coutb+col+1);
                float2 x0 = *(float2*)(x1_s + (m0+g  )*S_H + col);
                float2 x1v= *(float2*)(x1_s + (m0+g+8)*S_H + col);
                *(float2*)(y_s + (m0+g  )*S_H + col) = make_float2(co[j*4+0]+b0+x0.x,  co[j*4+1]+b1+x0.y);
                *(float2*)(y_s + (m0+g+8)*S_H + col) = make_float2(co[j*4+2]+b0+x1v.x, co[j*4+3]+b1+x1v.y);
            }
        }
        __syncthreads();

        {
            float4* og = (float4*)(out + t0 * CD);
            for (int q = tid; q < 2048; q += TPBW) {
                int r = q >> 6, c4 = q & 63;
                og[q] = ((float4*)y_s)[r*66 + c4];
            }
        }
        __syncthreads();
    }
}

extern "C" void kernel_launch(void* const* d_in, const int* in_sizes, int n_in,
                              void* d_out, int out_size)
{
    const float* x     = (const float*)d_in[0];
    const float* geom  = (const float*)d_in[1];
    const float* ln1g  = (const float*)d_in[2];
    const float* ln1b  = (const float*)d_in[3];
    const float* Wsh   = (const float*)d_in[4];
    const float* bsh   = (const float*)d_in[5];
    const float* Wf    = (const float*)d_in[6];
    const float* bf    = (const float*)d_in[7];
    const float* Wa    = (const float*)d_in[8];
    const float* ba    = (const float*)d_in[9];
    const float* ltdW  = (const float*)d_in[10];
    const float* ltdb  = (const float*)d_in[11];
    const float* dng   = (const float*)d_in[12];
    const float* dnb   = (const float*)d_in[13];
    const float* ancW  = (const float*)d_in[14];
    const float* ancb  = (const float*)d_in[15];
    const float* selfW = (const float*)d_in[16];
    const float* ctxW  = (const float*)d_in[17];
    const float* ong   = (const float*)d_in[18];
    const float* onb   = (const float*)d_in[19];
    const float* upW   = (const float*)d_in[20];
    const float* upb   = (const float*)d_in[21];
    const float* ln2g  = (const float*)d_in[22];
    const float* ln2b  = (const float*)d_in[23];
    const float* cinW  = (const float*)d_in[24];
    const float* cinb  = (const float*)d_in[25];
    const float* coutW = (const float*)d_in[26];
    const float* coutb = (const float*)d_in[27];
    float* out = (float*)d_out;

    const int smemA = (32*S_H + 32*S_L + 32*S_H + 32*S_L + 32*S_L + 16384 + 8192) * 4;
    const int smemB = (4096 + 4096 + 1024 + 1024 + 4096 + 16) * 4;
    const int smemC = (32*S_H + 32*S_H + 32*S_L + 32*S_VG + 16384 + 16384) * 4;

    cudaFuncSetAttribute(kA, cudaFuncAttributeMaxDynamicSharedMemorySize, smemA);
    cudaFuncSetAttribute(kB, cudaFuncAttributeMaxDynamicSharedMemorySize, smemB);
    cudaFuncSetAttribute(kC, cudaFuncAttributeMaxDynamicSharedMemorySize, smemC);

    kPack<<<64, 256>>>(Wsh,   0, 256,  64);
    kPack<<<64, 256>>>(Wf,    1,  64, 256);
    kPack<<<64, 256>>>(Wa,    2, 128,  64);
    kPack<<<64, 256>>>(cinW,  3, 256, 128);
    kPack<<<64, 256>>>(coutW, 4,  64, 256);
    kA<<<GRID_BN, TPBW, smemA>>>(x, geom, ln1g, ln1b, bsh, bf, ba);
    kR<<<NB*SD, TPB>>>();
    kB<<<NB, TPB, smemB>>>(ltdW, ltdb, dng, dnb, ancW, ancb, selfW, ctxW, ong, onb, upW, upb);
    kC<<<GRID_BN, TPBW, smemC>>>(x, out, ln2g, ln2b, cinb, coutb);

    (void)in_sizes; (void)n_in; (void)out_size;
}